// round 14
// baseline (speedup 1.0000x reference)
#include <cuda_runtime.h>
#include <math.h>
#include <stdint.h>

// ---------------------------------------------------------------------------
// CLFormer v14 for GB300 (sm_103a harness, base ISA).
// B=32, C=32, L=16384, H=4(dh=8), NB=3.
// v14 vs v13: FC pipeline processed in independent 16-token halves
// (FC1_m -> gelu -> FC2_m -> gelu), halving live accumulators (dacc[16]);
// __launch_bounds__(128,6) for 6 CTAs/SM (smem 36.3KB x6 = 218 <= 228KB).
// Launches: zero, stats_x, token0, token1, token2(last), final = 6.
// ---------------------------------------------------------------------------

#define Bn 32
#define Cn 32
#define Ln 16384
#define NCH 64          // chunks per batch row
#define CHT 256         // tokens per chunk
#define NTH 128
#define NGR 2           // groups of 128 tokens per chunk
#define HST 36          // row stride (floats): conflict-free, 16B-aligned

typedef unsigned long long u64;

__device__ float g_h[(size_t)Bn * Cn * Ln];     // 64MB: eh = exp(h) activations
__device__ float g_kvraw[3 * Bn * 288];         // per (buf,b): S[32] | M[256]
__device__ float g_pool[Bn * NCH * 32];

// ---- packed f32x2 helpers --------------------------------------------------
__device__ __forceinline__ u64 dup2(float a) {
    u64 r; asm("mov.b64 %0, {%1, %1};" : "=l"(r) : "f"(a)); return r;
}
__device__ __forceinline__ void fma2(u64& d, u64 a, u64 b) {
    asm("fma.rn.f32x2 %0, %1, %2, %0;" : "+l"(d) : "l"(a), "l"(b));
}
__device__ __forceinline__ u64 fma2g(u64 a, u64 b, u64 c) {
    u64 d; asm("fma.rn.f32x2 %0, %1, %2, %3;" : "=l"(d) : "l"(a), "l"(b), "l"(c));
    return d;
}
__device__ __forceinline__ u64 mul2(u64 a, u64 b) {
    u64 d; asm("mul.rn.f32x2 %0, %1, %2;" : "=l"(d) : "l"(a), "l"(b)); return d;
}
__device__ __forceinline__ float2 unpk(u64 v) {
    float2 f; asm("mov.b64 {%0, %1}, %2;" : "=f"(f.x), "=f"(f.y) : "l"(v)); return f;
}
__device__ __forceinline__ u64 pack2(float x, float y) {
    u64 r; asm("mov.b64 %0, {%1, %2};" : "=l"(r) : "f"(x), "f"(y)); return r;
}
__device__ __forceinline__ float frcp(float x) {
    float r; asm("rcp.approx.f32 %0, %1;" : "=f"(r) : "f"(x)); return r;
}
__device__ __forceinline__ uint32_t cvt_tf32(float x) {
    uint32_t r; asm("cvt.rna.tf32.f32 %0, %1;" : "=r"(r) : "f"(x)); return r;
}

// scalar GELU (A&S 7.1.28, max abs err 3e-7) — small kernels only
__device__ __forceinline__ float gelu_f(float x) {
    float z = fabsf(x) * 0.7071067811865476f;
    float u = fmaf(z, fmaf(z, fmaf(z, fmaf(z, fmaf(z, fmaf(z,
                  4.30638e-5f, 2.765672e-4f), 1.520143e-4f),
                  9.2705272e-3f), 4.22820123e-2f), 7.05230784e-2f), 1.0f);
    float t = frcp(u);
    float t2 = t * t, t4 = t2 * t2, t8 = t4 * t4, t16 = t8 * t8;
    float er = copysignf(1.0f - t16, x);
    return 0.5f * x * (1.0f + er);
}

// packed GELU (A&S 7.1.28), trimmed epilogue: res = er*hx + hx, hx = 0.5x
__device__ __forceinline__ u64 gelu2(u64 x) {
    u64 sg = x & 0x8000000080000000ull;
    u64 ax = x ^ sg;
    u64 z  = mul2(ax, dup2(0.7071067811865476f));
    u64 u  = fma2g(z, dup2(4.30638e-5f), dup2(2.765672e-4f));
    u = fma2g(z, u, dup2(1.520143e-4f));
    u = fma2g(z, u, dup2(9.2705272e-3f));
    u = fma2g(z, u, dup2(4.22820123e-2f));
    u = fma2g(z, u, dup2(7.05230784e-2f));
    u = fma2g(z, u, dup2(1.0f));
    float2 uf = unpk(u);
    u64 t  = pack2(frcp(uf.x), frcp(uf.y));
    u64 t2 = mul2(t, t);
    u64 t4 = mul2(t2, t2);
    u64 t8 = mul2(t4, t4);
    u64 t16 = mul2(t8, t8);
    u64 er = fma2g(t16, dup2(-1.0f), dup2(1.0f)) | sg;
    u64 hx = mul2(x, dup2(0.5f));
    return fma2g(er, hx, hx);
}

// ---- mma.sync m16n8k8 tf32 (row.col), D += A@B ------------------------------
__device__ __forceinline__ void mma8(float& d0, float& d1, float& d2, float& d3,
        uint32_t a0, uint32_t a1, uint32_t a2, uint32_t a3, uint2 bb) {
    asm volatile(
        "mma.sync.aligned.m16n8k8.row.col.f32.tf32.tf32.f32 "
        "{%0,%1,%2,%3}, {%4,%5,%6,%7}, {%8,%9}, {%0,%1,%2,%3};"
        : "+f"(d0), "+f"(d1), "+f"(d2), "+f"(d3)
        : "r"(a0), "r"(a1), "r"(a2), "r"(a3), "r"(bb.x), "r"(bb.y));
}

// One 16x32x32 FC half-tile (m16) for token rows [rowbase, rowbase+16).
// dacc[16] = 4 nt-tiles. Bh/Bl: fragment-ordered smem [16 (kt*4+nt)][32 lanes].
__device__ __forceinline__ void fc_mma_m(const uint32_t* Su, int rowbase,
        int g, int t, int lane, const uint2* Bh, const uint2* Bl,
        const float* sb, float* dacc) {
#pragma unroll
    for (int nt = 0; nt < 4; nt++) {
        float b0 = sb[nt * 8 + 2 * t], b1 = sb[nt * 8 + 2 * t + 1];
        dacc[nt*4+0] = b0; dacc[nt*4+1] = b1; dacc[nt*4+2] = b0; dacc[nt*4+3] = b1;
    }
#pragma unroll
    for (int kt = 0; kt < 4; kt++) {
        const uint32_t* r0 = Su + (rowbase + g) * HST + kt * 8 + t;
        uint32_t A0 = r0[0], A1 = r0[8 * HST], A2 = r0[4], A3 = r0[8 * HST + 4];
#pragma unroll
        for (int nt = 0; nt < 4; nt++) {
            uint2 bh = Bh[(kt * 4 + nt) * 32 + lane];
            uint2 bl = Bl[(kt * 4 + nt) * 32 + lane];
            mma8(dacc[nt*4], dacc[nt*4+1], dacc[nt*4+2], dacc[nt*4+3],
                 A0, A1, A2, A3, bh);
            mma8(dacc[nt*4], dacc[nt*4+1], dacc[nt*4+2], dacc[nt*4+3],
                 A0, A1, A2, A3, bl);
        }
    }
}

// ---- staging / stats ----------------------------------------------------------
__device__ __forceinline__ void stage_row(float* S, int tid, const float (&v)[32]) {
    float4* d = reinterpret_cast<float4*>(S + tid * HST);
#pragma unroll
    for (int k = 0; k < 8; k++)
        d[k] = make_float4(v[4 * k], v[4 * k + 1], v[4 * k + 2], v[4 * k + 3]);
}

// thread owns M row r over its warp's 32 rows (warp-local); exp inline.
__device__ __forceinline__ void accum_stats(const float* hS, int r, int q,
        u64& m0, u64& m1, u64& m2, u64& m3, float& sacc) {
    const float* ph = hS + q * 32 * HST;
    const int eoff = (r & 24);
#pragma unroll 4
    for (int s = 0; s < 32; s++) {
        float ed = __expf(ph[r]);
        ulonglong2 hv = *reinterpret_cast<const ulonglong2*>(ph + eoff);
        ulonglong2 hw = *reinterpret_cast<const ulonglong2*>(ph + eoff + 4);
        u64 e2 = dup2(ed);
        fma2(m0, e2, hv.x); fma2(m1, e2, hv.y);
        fma2(m2, e2, hw.x); fma2(m3, e2, hw.y);
        sacc += ed;
        ph += HST;
    }
}

__device__ __forceinline__ void stats_atomic_out(float* red, float* gout, int tid,
        u64 m0, u64 m1, u64 m2, u64 m3, float sacc) {
    __syncthreads();
    int r = tid & 31, q = tid >> 5;
    float2 a = unpk(m0), b = unpk(m1), c = unpk(m2), d = unpk(m3);
    float4* dst = reinterpret_cast<float4*>(red + q * 288 + r * 8);
    dst[0] = make_float4(a.x, a.y, b.x, b.y);
    dst[1] = make_float4(c.x, c.y, d.x, d.y);
    red[q * 288 + 256 + r] = sacc;
    __syncthreads();
    float M0 = red[tid] + red[288 + tid] + red[576 + tid] + red[864 + tid];
    float M1 = red[128 + tid] + red[416 + tid] + red[704 + tid] + red[992 + tid];
    atomicAdd(&gout[32 + tid], M0);
    atomicAdd(&gout[160 + tid], M1);
    if (tid < 32) {
        float S = red[256 + tid] + red[544 + tid] + red[832 + tid] + red[1120 + tid];
        atomicAdd(&gout[tid], S);
    }
}

// ---------------------------------------------------------------------------
__global__ void zero_kernel() {
    int i = blockIdx.x * 256 + threadIdx.x;
    if (i < 3 * Bn * 288) g_kvraw[i] = 0.f;
}

// ---------------------------------------------------------------------------
// Kernel 1: stats over raw x (warp-local); writes eh(x); atomics buf 0.
// ---------------------------------------------------------------------------
__global__ __launch_bounds__(NTH, 5) void stats_x_kernel(const float* __restrict__ x) {
    __shared__ __align__(16) float hS[NTH * HST];
    int tid = threadIdx.x, b = blockIdx.y, ch = blockIdx.x;
    int lane = tid & 31, q = tid >> 5;
    const float* xb = x + (size_t)b * Cn * Ln + ch * CHT;
    float* outb = g_h + (size_t)b * Cn * Ln + ch * CHT;
    u64 m0 = 0, m1 = 0, m2 = 0, m3 = 0; float sacc = 0.f;
    for (int g = 0; g < NGR; g++) {
        int l = g * NTH + tid;
        float h[32];
#pragma unroll
        for (int c = 0; c < 32; c++) h[c] = xb[(size_t)c * Ln + l];
#pragma unroll
        for (int c = 0; c < 32; c++)
            outb[(size_t)c * Ln + l] = __expf(h[c]);
        __syncwarp();
        stage_row(hS, tid, h);
        __syncwarp();
        accum_stats(hS, lane, q, m0, m1, m2, m3, sacc);
        __syncwarp();
    }
    stats_atomic_out(hS, g_kvraw + (size_t)b * 288, tid, m0, m1, m2, m3, sacc);
}

// ---------------------------------------------------------------------------
// Kernel 2: token pass — q-scale + FC1(W1eff=KV@W1) + FC2, all mma.sync tf32,
// processed in independent 16-token halves.
// ---------------------------------------------------------------------------
template <int BUFIN, bool LAST>
__global__ __launch_bounds__(NTH, 6) void token_kernel(
        const float* __restrict__ W1, const float* __restrict__ b1,
        const float* __restrict__ W2, const float* __restrict__ b2) {
    __shared__ __align__(16) float hS[NTH * HST];        // token rows / W1eff temp
    __shared__ __align__(16) uint2 sB1h[512], sB1l[512]; // FC B frags [16][32]
    __shared__ __align__(16) uint2 sB2h[512], sB2l[512];
    __shared__ __align__(16) float skv[256];
    __shared__ float sS[32], sb1[32], sb2[32];

    int tid = threadIdx.x, b = blockIdx.y, ch = blockIdx.x;
    int lane = tid & 31, q = tid >> 5;
    int g = lane >> 2, t = lane & 3;
    int wb = q * 32;
    uint32_t* Su = reinterpret_cast<uint32_t*>(hS);

    // ---- prologue 1: kv finish ----
    const float* kvin = g_kvraw + ((size_t)BUFIN * Bn + b) * 288;
    float M0 = kvin[32 + tid], M1 = kvin[160 + tid];
    if (tid < 32) { sS[tid] = kvin[tid]; sb1[tid] = b1[tid]; sb2[tid] = b2[tid]; }
    // W2 fragments straight from gmem
#pragma unroll
    for (int ii = 0; ii < 4; ii++) {
        int idx = q * 4 + ii;               // kt = idx>>2, nt = idx&3
        int krow = (idx >> 2) * 8 + t;
        int ncol = (idx & 3) * 8 + g;
        float w0 = W2[krow * 32 + ncol];
        float w1 = W2[(krow + 4) * 32 + ncol];
        uint32_t h0 = cvt_tf32(w0), h1 = cvt_tf32(w1);
        sB2h[idx * 32 + lane] = make_uint2(h0, h1);
        sB2l[idx * 32 + lane] = make_uint2(cvt_tf32(w0 - __uint_as_float(h0)),
                                           cvt_tf32(w1 - __uint_as_float(h1)));
    }
    __syncthreads();
    {
        int u0 = tid, u1 = tid + 128;
        int cd0 = ((u0 >> 6) << 3) | ((u0 >> 3) & 7);
        int cd1 = ((u1 >> 6) << 3) | ((u1 >> 3) & 7);
        skv[u0] = M0 / sS[cd0];
        skv[u1] = M1 / sS[cd1];
    }
    __syncthreads();

    // ---- prologue 2: W1eff = blockdiag(kv) @ W1, fp32, into hS temp ----
    {
        int row = tid >> 2;                 // 0..31 (d global)
        int jb4 = (tid & 3) * 8;            // 8 cols
        int hd = row >> 3, dl = row & 7;
        float acc[8] = {0.f, 0.f, 0.f, 0.f, 0.f, 0.f, 0.f, 0.f};
#pragma unroll
        for (int e = 0; e < 8; e++) {
            float kvv = skv[hd * 64 + dl * 8 + e];
            const float* wr = W1 + (hd * 8 + e) * 32 + jb4;
#pragma unroll
            for (int jj = 0; jj < 8; jj++) acc[jj] = fmaf(kvv, wr[jj], acc[jj]);
        }
#pragma unroll
        for (int jj = 0; jj < 8; jj++) hS[row * 32 + jb4 + jj] = acc[jj];
    }
    __syncthreads();
    // W1eff fragments (hi/lo) from hS
#pragma unroll
    for (int ii = 0; ii < 4; ii++) {
        int idx = q * 4 + ii;
        int krow = (idx >> 2) * 8 + t;
        int ncol = (idx & 3) * 8 + g;
        float w0 = hS[krow * 32 + ncol];
        float w1 = hS[(krow + 4) * 32 + ncol];
        uint32_t h0 = cvt_tf32(w0), h1 = cvt_tf32(w1);
        sB1h[idx * 32 + lane] = make_uint2(h0, h1);
        sB1l[idx * 32 + lane] = make_uint2(cvt_tf32(w0 - __uint_as_float(h0)),
                                           cvt_tf32(w1 - __uint_as_float(h1)));
    }
    __syncthreads();   // fragments done; hS free for token rows

    u64 m0 = 0, m1 = 0, m2 = 0, m3 = 0; float sacc = 0.f, pacc = 0.f;
    const float* inb = g_h + (size_t)b * Cn * Ln + ch * CHT;
    float* outb = g_h + (size_t)b * Cn * Ln + ch * CHT;

    for (int grp = 0; grp < NGR; grp++) {
        int l = grp * NTH + tid;
        float eh[32];
#pragma unroll
        for (int c = 0; c < 32; c++) eh[c] = inb[(size_t)c * Ln + l];

        // head sums -> inv; scale eh in registers -> q; stage q as tf32 rows
        float iv[4];
        {
            float s;
            s = eh[0]+eh[1]+eh[2]+eh[3]+eh[4]+eh[5]+eh[6]+eh[7];         iv[0] = frcp(s);
            s = eh[8]+eh[9]+eh[10]+eh[11]+eh[12]+eh[13]+eh[14]+eh[15];   iv[1] = frcp(s);
            s = eh[16]+eh[17]+eh[18]+eh[19]+eh[20]+eh[21]+eh[22]+eh[23]; iv[2] = frcp(s);
            s = eh[24]+eh[25]+eh[26]+eh[27]+eh[28]+eh[29]+eh[30]+eh[31]; iv[3] = frcp(s);
        }
        __syncwarp();   // prior-group row reads done
        {
            uint4* d4 = reinterpret_cast<uint4*>(Su + tid * HST);
#pragma unroll
            for (int k = 0; k < 8; k++) {
                float inv = iv[k >> 1];
                d4[k] = make_uint4(cvt_tf32(eh[4 * k] * inv),
                                   cvt_tf32(eh[4 * k + 1] * inv),
                                   cvt_tf32(eh[4 * k + 2] * inv),
                                   cvt_tf32(eh[4 * k + 3] * inv));
            }
        }
        __syncwarp();

        // ---- per 16-token half: FC1 -> gelu -> FC2 -> gelu ----
#pragma unroll
        for (int m = 0; m < 2; m++) {
            const int rowbase = wb + m * 16;
            float dacc[16];

            // FC1 on W1eff (attention folded) + gelu -> restage tf32
            fc_mma_m(Su, rowbase, g, t, lane, sB1h, sB1l, sb1, dacc);
            __syncwarp();
            {
                uint32_t* base0 = Su + (rowbase + g) * HST + 2 * t;
                uint32_t* base2 = base0 + 8 * HST;
#pragma unroll
                for (int nt = 0; nt < 4; nt++) {
                    float* d = dacc + nt * 4;
                    float2 f01 = unpk(gelu2(pack2(d[0], d[1])));
                    float2 f23 = unpk(gelu2(pack2(d[2], d[3])));
                    *reinterpret_cast<uint2*>(base0 + nt * 8) =
                        make_uint2(cvt_tf32(f01.x), cvt_tf32(f01.y));
                    *reinterpret_cast<uint2*>(base2 + nt * 8) =
                        make_uint2(cvt_tf32(f23.x), cvt_tf32(f23.y));
                }
            }
            __syncwarp();

            // FC2 + gelu -> stage h rows (f32)
            fc_mma_m(Su, rowbase, g, t, lane, sB2h, sB2l, sb2, dacc);
            __syncwarp();
            {
                float* base0 = hS + (rowbase + g) * HST + 2 * t;
                float* base2 = base0 + 8 * HST;
#pragma unroll
                for (int nt = 0; nt < 4; nt++) {
                    float* d = dacc + nt * 4;
                    float2 f01 = unpk(gelu2(pack2(d[0], d[1])));
                    float2 f23 = unpk(gelu2(pack2(d[2], d[3])));
                    *reinterpret_cast<float2*>(base0 + nt * 8) = f01;
                    *reinterpret_cast<float2*>(base2 + nt * 8) = f23;
                }
            }
            __syncwarp();
        }

        if (!LAST) {
            const float4* s4 = reinterpret_cast<const float4*>(hS + tid * HST);
#pragma unroll
            for (int k = 0; k < 8; k++) {
                float4 v = s4[k];
                outb[(size_t)(4 * k + 0) * Ln + l] = __expf(v.x);
                outb[(size_t)(4 * k + 1) * Ln + l] = __expf(v.y);
                outb[(size_t)(4 * k + 2) * Ln + l] = __expf(v.z);
                outb[(size_t)(4 * k + 3) * Ln + l] = __expf(v.w);
            }
            accum_stats(hS, lane, q, m0, m1, m2, m3, sacc);
            __syncwarp();
        } else {
            const float* p = hS + q * 32 * HST;
#pragma unroll 8
            for (int s = 0; s < 32; s++) { pacc += p[lane]; p += HST; }
            __syncwarp();
        }
    }

    if (!LAST) {
        stats_atomic_out(hS, g_kvraw + ((size_t)(BUFIN + 1) * Bn + b) * 288,
                         tid, m0, m1, m2, m3, sacc);
    } else {
        __syncthreads();
        hS[q * 32 + lane] = pacc;
        __syncthreads();
        if (tid < 32)
            g_pool[(size_t)(b * NCH + ch) * 32 + tid] =
                hS[tid] + hS[32 + tid] + hS[64 + tid] + hS[96 + tid];
    }
}

// ---------------------------------------------------------------------------
// Kernel 3: head (pool-finish, Linear, BN(eval), GELU, Linear)
// ---------------------------------------------------------------------------
__global__ __launch_bounds__(32) void final_kernel(
        const float* __restrict__ Wh, const float* __restrict__ bh,
        const float* __restrict__ gamma, const float* __restrict__ beta,
        const float* __restrict__ mu, const float* __restrict__ var,
        const float* __restrict__ Wf, const float* __restrict__ bf,
        float* __restrict__ out) {
    int b = threadIdx.x;
    if (b >= Bn) return;
    float p[32];
#pragma unroll
    for (int c = 0; c < 32; c++) {
        float sum = 0.f;
        for (int ch = 0; ch < NCH; ch++)
            sum += g_pool[(size_t)(b * NCH + ch) * 32 + c];
        p[c] = sum * (1.0f / (float)Ln);
    }
    float z[32];
#pragma unroll
    for (int j = 0; j < 32; j++) {
        float sv = bh[j];
#pragma unroll
        for (int c = 0; c < 32; c++) sv += p[c] * Wh[c * 32 + j];
        sv = (sv - mu[j]) * rsqrtf(var[j] + 1e-5f) * gamma[j] + beta[j];
        z[j] = 0.5f * sv * (1.0f + erff(sv * 0.7071067811865476f));
    }
    for (int k = 0; k < 10; k++) {
        float sv = bf[k];
#pragma unroll
        for (int j = 0; j < 32; j++) sv += z[j] * Wf[j * 10 + k];
        out[b * 10 + k] = sv;
    }
}

// ---------------------------------------------------------------------------
extern "C" void kernel_launch(void* const* d_in, const int* in_sizes, int n_in,
                              void* d_out, int out_size) {
    const float* x    = (const float*)d_in[0];
    const float* fcW1 = (const float*)d_in[1];
    const float* fcb1 = (const float*)d_in[2];
    const float* fcW2 = (const float*)d_in[3];
    const float* fcb2 = (const float*)d_in[4];
    const float* Wh   = (const float*)d_in[5];
    const float* bh   = (const float*)d_in[6];
    const float* gam  = (const float*)d_in[7];
    const float* bet  = (const float*)d_in[8];
    const float* mu   = (const float*)d_in[9];
    const float* var  = (const float*)d_in[10];
    const float* Wf   = (const float*)d_in[11];
    const float* bf   = (const float*)d_in[12];
    float* out = (float*)d_out;

    dim3 grid(NCH, Bn);
    zero_kernel<<<(3 * Bn * 288 + 255) / 256, 256>>>();
    stats_x_kernel<<<grid, NTH>>>(x);
    token_kernel<0, false><<<grid, NTH>>>(fcW1, fcb1, fcW2, fcb2);
    token_kernel<1, false><<<grid, NTH>>>(fcW1 + 1024, fcb1 + 32,
                                          fcW2 + 1024, fcb2 + 32);
    token_kernel<2, true ><<<grid, NTH>>>(fcW1 + 2048, fcb1 + 64,
                                          fcW2 + 2048, fcb2 + 64);
    final_kernel<<<1, 32>>>(Wh, bh, gam, bet, mu, var, Wf, bf, out);
}

// round 15
// speedup vs baseline: 1.0200x; 1.0200x over previous
#include <cuda_runtime.h>
#include <math.h>
#include <stdint.h>

// ---------------------------------------------------------------------------
// CLFormer v15 for GB300 (sm_103a harness, base ISA).
// B=32, C=32, L=16384, H=4(dh=8), NB=3.
// v15 vs v13 (best, 275.2us):
//  - B fragments packed hi+lo in one uint4 (1 LDS.128/tile vs 2 LDS.64)
//  - stats_x no longer writes eh; token0 reads x and computes eh inline
//    (saves a 64MB DRAM write)
//  - v14's m-split reverted (shared-path traffic, not occupancy, binds)
// Launches: zero, stats_x, token0, token1, token2(last), final = 6.
// ---------------------------------------------------------------------------

#define Bn 32
#define Cn 32
#define Ln 16384
#define NCH 64          // chunks per batch row
#define CHT 256         // tokens per chunk
#define NTH 128
#define NGR 2           // groups of 128 tokens per chunk
#define HST 36          // row stride (floats): conflict-free, 16B-aligned

typedef unsigned long long u64;

__device__ float g_h[(size_t)Bn * Cn * Ln];     // 64MB: eh = exp(h) activations
__device__ float g_kvraw[3 * Bn * 288];         // per (buf,b): S[32] | M[256]
__device__ float g_pool[Bn * NCH * 32];

// ---- packed f32x2 helpers --------------------------------------------------
__device__ __forceinline__ u64 dup2(float a) {
    u64 r; asm("mov.b64 %0, {%1, %1};" : "=l"(r) : "f"(a)); return r;
}
__device__ __forceinline__ void fma2(u64& d, u64 a, u64 b) {
    asm("fma.rn.f32x2 %0, %1, %2, %0;" : "+l"(d) : "l"(a), "l"(b));
}
__device__ __forceinline__ u64 fma2g(u64 a, u64 b, u64 c) {
    u64 d; asm("fma.rn.f32x2 %0, %1, %2, %3;" : "=l"(d) : "l"(a), "l"(b), "l"(c));
    return d;
}
__device__ __forceinline__ u64 mul2(u64 a, u64 b) {
    u64 d; asm("mul.rn.f32x2 %0, %1, %2;" : "=l"(d) : "l"(a), "l"(b)); return d;
}
__device__ __forceinline__ float2 unpk(u64 v) {
    float2 f; asm("mov.b64 {%0, %1}, %2;" : "=f"(f.x), "=f"(f.y) : "l"(v)); return f;
}
__device__ __forceinline__ u64 pack2(float x, float y) {
    u64 r; asm("mov.b64 %0, {%1, %2};" : "=l"(r) : "f"(x), "f"(y)); return r;
}
__device__ __forceinline__ float frcp(float x) {
    float r; asm("rcp.approx.f32 %0, %1;" : "=f"(r) : "f"(x)); return r;
}
__device__ __forceinline__ uint32_t cvt_tf32(float x) {
    uint32_t r; asm("cvt.rna.tf32.f32 %0, %1;" : "=r"(r) : "f"(x)); return r;
}

// scalar GELU (A&S 7.1.28, max abs err 3e-7) — small kernels only
__device__ __forceinline__ float gelu_f(float x) {
    float z = fabsf(x) * 0.7071067811865476f;
    float u = fmaf(z, fmaf(z, fmaf(z, fmaf(z, fmaf(z, fmaf(z,
                  4.30638e-5f, 2.765672e-4f), 1.520143e-4f),
                  9.2705272e-3f), 4.22820123e-2f), 7.05230784e-2f), 1.0f);
    float t = frcp(u);
    float t2 = t * t, t4 = t2 * t2, t8 = t4 * t4, t16 = t8 * t8;
    float er = copysignf(1.0f - t16, x);
    return 0.5f * x * (1.0f + er);
}

// packed GELU (A&S 7.1.28), trimmed epilogue: res = er*hx + hx, hx = 0.5x
__device__ __forceinline__ u64 gelu2(u64 x) {
    u64 sg = x & 0x8000000080000000ull;
    u64 ax = x ^ sg;
    u64 z  = mul2(ax, dup2(0.7071067811865476f));
    u64 u  = fma2g(z, dup2(4.30638e-5f), dup2(2.765672e-4f));
    u = fma2g(z, u, dup2(1.520143e-4f));
    u = fma2g(z, u, dup2(9.2705272e-3f));
    u = fma2g(z, u, dup2(4.22820123e-2f));
    u = fma2g(z, u, dup2(7.05230784e-2f));
    u = fma2g(z, u, dup2(1.0f));
    float2 uf = unpk(u);
    u64 t  = pack2(frcp(uf.x), frcp(uf.y));
    u64 t2 = mul2(t, t);
    u64 t4 = mul2(t2, t2);
    u64 t8 = mul2(t4, t4);
    u64 t16 = mul2(t8, t8);
    u64 er = fma2g(t16, dup2(-1.0f), dup2(1.0f)) | sg;
    u64 hx = mul2(x, dup2(0.5f));
    return fma2g(er, hx, hx);
}

// ---- mma.sync m16n8k8 tf32 (row.col), D += A@B ------------------------------
__device__ __forceinline__ void mma8(float& d0, float& d1, float& d2, float& d3,
        uint32_t a0, uint32_t a1, uint32_t a2, uint32_t a3,
        uint32_t b0, uint32_t b1) {
    asm volatile(
        "mma.sync.aligned.m16n8k8.row.col.f32.tf32.tf32.f32 "
        "{%0,%1,%2,%3}, {%4,%5,%6,%7}, {%8,%9}, {%0,%1,%2,%3};"
        : "+f"(d0), "+f"(d1), "+f"(d2), "+f"(d3)
        : "r"(a0), "r"(a1), "r"(a2), "r"(a3), "r"(b0), "r"(b1));
}

// One 32x32x32 FC for this warp's 32 token rows (tf32 bits in Su rows).
// B: fragment-ordered smem [16 (kt*4+nt)][32 lanes] of uint4 {hi0,hi1,lo0,lo1}.
__device__ __forceinline__ void fc_mma(const uint32_t* Su, int wb, int g, int t,
        int lane, const uint4* B, const float* sb, float* dacc) {
#pragma unroll
    for (int nt = 0; nt < 4; nt++) {
        float b0 = sb[nt * 8 + 2 * t], b1 = sb[nt * 8 + 2 * t + 1];
        dacc[nt*4+0] = b0; dacc[nt*4+1] = b1; dacc[nt*4+2] = b0; dacc[nt*4+3] = b1;
        dacc[16+nt*4+0] = b0; dacc[16+nt*4+1] = b1; dacc[16+nt*4+2] = b0; dacc[16+nt*4+3] = b1;
    }
#pragma unroll
    for (int kt = 0; kt < 4; kt++) {
        const uint32_t* r0 = Su + (wb + g) * HST + kt * 8 + t;
        uint32_t A00 = r0[0], A01 = r0[8 * HST], A02 = r0[4], A03 = r0[8 * HST + 4];
        const uint32_t* r1 = r0 + 16 * HST;
        uint32_t A10 = r1[0], A11 = r1[8 * HST], A12 = r1[4], A13 = r1[8 * HST + 4];
#pragma unroll
        for (int nt = 0; nt < 4; nt++) {
            uint4 bb = B[(kt * 4 + nt) * 32 + lane];
            mma8(dacc[nt*4], dacc[nt*4+1], dacc[nt*4+2], dacc[nt*4+3],
                 A00, A01, A02, A03, bb.x, bb.y);
            mma8(dacc[nt*4], dacc[nt*4+1], dacc[nt*4+2], dacc[nt*4+3],
                 A00, A01, A02, A03, bb.z, bb.w);
            mma8(dacc[16+nt*4], dacc[16+nt*4+1], dacc[16+nt*4+2], dacc[16+nt*4+3],
                 A10, A11, A12, A13, bb.x, bb.y);
            mma8(dacc[16+nt*4], dacc[16+nt*4+1], dacc[16+nt*4+2], dacc[16+nt*4+3],
                 A10, A11, A12, A13, bb.z, bb.w);
        }
    }
}

// ---- staging / stats ----------------------------------------------------------
__device__ __forceinline__ void stage_row(float* S, int tid, const float (&v)[32]) {
    float4* d = reinterpret_cast<float4*>(S + tid * HST);
#pragma unroll
    for (int k = 0; k < 8; k++)
        d[k] = make_float4(v[4 * k], v[4 * k + 1], v[4 * k + 2], v[4 * k + 3]);
}

// thread owns M row r over its warp's 32 rows (warp-local); exp inline.
__device__ __forceinline__ void accum_stats(const float* hS, int r, int q,
        u64& m0, u64& m1, u64& m2, u64& m3, float& sacc) {
    const float* ph = hS + q * 32 * HST;
    const int eoff = (r & 24);
#pragma unroll 4
    for (int s = 0; s < 32; s++) {
        float ed = __expf(ph[r]);
        ulonglong2 hv = *reinterpret_cast<const ulonglong2*>(ph + eoff);
        ulonglong2 hw = *reinterpret_cast<const ulonglong2*>(ph + eoff + 4);
        u64 e2 = dup2(ed);
        fma2(m0, e2, hv.x); fma2(m1, e2, hv.y);
        fma2(m2, e2, hw.x); fma2(m3, e2, hw.y);
        sacc += ed;
        ph += HST;
    }
}

__device__ __forceinline__ void stats_atomic_out(float* red, float* gout, int tid,
        u64 m0, u64 m1, u64 m2, u64 m3, float sacc) {
    __syncthreads();
    int r = tid & 31, q = tid >> 5;
    float2 a = unpk(m0), b = unpk(m1), c = unpk(m2), d = unpk(m3);
    float4* dst = reinterpret_cast<float4*>(red + q * 288 + r * 8);
    dst[0] = make_float4(a.x, a.y, b.x, b.y);
    dst[1] = make_float4(c.x, c.y, d.x, d.y);
    red[q * 288 + 256 + r] = sacc;
    __syncthreads();
    float M0 = red[tid] + red[288 + tid] + red[576 + tid] + red[864 + tid];
    float M1 = red[128 + tid] + red[416 + tid] + red[704 + tid] + red[992 + tid];
    atomicAdd(&gout[32 + tid], M0);
    atomicAdd(&gout[160 + tid], M1);
    if (tid < 32) {
        float S = red[256 + tid] + red[544 + tid] + red[832 + tid] + red[1120 + tid];
        atomicAdd(&gout[tid], S);
    }
}

// ---------------------------------------------------------------------------
__global__ void zero_kernel() {
    int i = blockIdx.x * 256 + threadIdx.x;
    if (i < 3 * Bn * 288) g_kvraw[i] = 0.f;
}

// ---------------------------------------------------------------------------
// Kernel 1: stats over raw x (warp-local). No eh write (token0 reads x).
// ---------------------------------------------------------------------------
__global__ __launch_bounds__(NTH, 5) void stats_x_kernel(const float* __restrict__ x) {
    __shared__ __align__(16) float hS[NTH * HST];
    int tid = threadIdx.x, b = blockIdx.y, ch = blockIdx.x;
    int lane = tid & 31, q = tid >> 5;
    const float* xb = x + (size_t)b * Cn * Ln + ch * CHT;
    u64 m0 = 0, m1 = 0, m2 = 0, m3 = 0; float sacc = 0.f;
    for (int g = 0; g < NGR; g++) {
        int l = g * NTH + tid;
        float h[32];
#pragma unroll
        for (int c = 0; c < 32; c++) h[c] = xb[(size_t)c * Ln + l];
        __syncwarp();
        stage_row(hS, tid, h);
        __syncwarp();
        accum_stats(hS, lane, q, m0, m1, m2, m3, sacc);
        __syncwarp();
    }
    stats_atomic_out(hS, g_kvraw + (size_t)b * 288, tid, m0, m1, m2, m3, sacc);
}

// ---------------------------------------------------------------------------
// Kernel 2: token pass — q-scale + FC1(W1eff=KV@W1) + FC2, all mma.sync tf32.
// FROM_X: read raw x and compute eh inline (block 0).
// ---------------------------------------------------------------------------
template <int BUFIN, bool LAST, bool FROM_X>
__global__ __launch_bounds__(NTH, 5) void token_kernel(
        const float* __restrict__ xin,
        const float* __restrict__ W1, const float* __restrict__ b1,
        const float* __restrict__ W2, const float* __restrict__ b2) {
    __shared__ __align__(16) float hS[NTH * HST];        // token rows / W1eff temp
    __shared__ __align__(16) uint4 sB1[512], sB2[512];   // FC B frags [16][32] hi+lo
    __shared__ __align__(16) float skv[256];
    __shared__ float sS[32], sb1[32], sb2[32];

    int tid = threadIdx.x, b = blockIdx.y, ch = blockIdx.x;
    int lane = tid & 31, q = tid >> 5;
    int g = lane >> 2, t = lane & 3;
    int wb = q * 32;
    uint32_t* Su = reinterpret_cast<uint32_t*>(hS);

    // ---- prologue 1: kv finish ----
    const float* kvin = g_kvraw + ((size_t)BUFIN * Bn + b) * 288;
    float M0 = kvin[32 + tid], M1 = kvin[160 + tid];
    if (tid < 32) { sS[tid] = kvin[tid]; sb1[tid] = b1[tid]; sb2[tid] = b2[tid]; }
    // W2 fragments straight from gmem (hi+lo packed)
#pragma unroll
    for (int ii = 0; ii < 4; ii++) {
        int idx = q * 4 + ii;               // kt = idx>>2, nt = idx&3
        int krow = (idx >> 2) * 8 + t;
        int ncol = (idx & 3) * 8 + g;
        float w0 = W2[krow * 32 + ncol];
        float w1 = W2[(krow + 4) * 32 + ncol];
        uint32_t h0 = cvt_tf32(w0), h1 = cvt_tf32(w1);
        sB2[idx * 32 + lane] = make_uint4(h0, h1,
                                          cvt_tf32(w0 - __uint_as_float(h0)),
                                          cvt_tf32(w1 - __uint_as_float(h1)));
    }
    __syncthreads();
    {
        int u0 = tid, u1 = tid + 128;
        int cd0 = ((u0 >> 6) << 3) | ((u0 >> 3) & 7);
        int cd1 = ((u1 >> 6) << 3) | ((u1 >> 3) & 7);
        skv[u0] = M0 / sS[cd0];
        skv[u1] = M1 / sS[cd1];
    }
    __syncthreads();

    // ---- prologue 2: W1eff = blockdiag(kv) @ W1, fp32, into hS temp ----
    {
        int row = tid >> 2;                 // 0..31 (d global)
        int jb4 = (tid & 3) * 8;            // 8 cols
        int hd = row >> 3, dl = row & 7;
        float acc[8] = {0.f, 0.f, 0.f, 0.f, 0.f, 0.f, 0.f, 0.f};
#pragma unroll
        for (int e = 0; e < 8; e++) {
            float kvv = skv[hd * 64 + dl * 8 + e];
            const float* wr = W1 + (hd * 8 + e) * 32 + jb4;
#pragma unroll
            for (int jj = 0; jj < 8; jj++) acc[jj] = fmaf(kvv, wr[jj], acc[jj]);
        }
#pragma unroll
        for (int jj = 0; jj < 8; jj++) hS[row * 32 + jb4 + jj] = acc[jj];
    }
    __syncthreads();
    // W1eff fragments (hi+lo packed) from hS
#pragma unroll
    for (int ii = 0; ii < 4; ii++) {
        int idx = q * 4 + ii;
        int krow = (idx >> 2) * 8 + t;
        int ncol = (idx & 3) * 8 + g;
        float w0 = hS[krow * 32 + ncol];
        float w1 = hS[(krow + 4) * 32 + ncol];
        uint32_t h0 = cvt_tf32(w0), h1 = cvt_tf32(w1);
        sB1[idx * 32 + lane] = make_uint4(h0, h1,
                                          cvt_tf32(w0 - __uint_as_float(h0)),
                                          cvt_tf32(w1 - __uint_as_float(h1)));
    }
    __syncthreads();   // fragments done; hS free for token rows

    u64 m0 = 0, m1 = 0, m2 = 0, m3 = 0; float sacc = 0.f, pacc = 0.f;
    const float* inb = FROM_X ? (xin + (size_t)b * Cn * Ln + ch * CHT)
                              : (g_h + (size_t)b * Cn * Ln + ch * CHT);
    float* outb = g_h + (size_t)b * Cn * Ln + ch * CHT;

    for (int grp = 0; grp < NGR; grp++) {
        int l = grp * NTH + tid;
        float eh[32];
        if (FROM_X) {
#pragma unroll
            for (int c = 0; c < 32; c++) eh[c] = __expf(inb[(size_t)c * Ln + l]);
        } else {
#pragma unroll
            for (int c = 0; c < 32; c++) eh[c] = inb[(size_t)c * Ln + l];
        }

        // head sums -> inv; scale eh in registers -> q; stage q as tf32 rows
        float iv[4];
        {
            float s;
            s = eh[0]+eh[1]+eh[2]+eh[3]+eh[4]+eh[5]+eh[6]+eh[7];         iv[0] = frcp(s);
            s = eh[8]+eh[9]+eh[10]+eh[11]+eh[12]+eh[13]+eh[14]+eh[15];   iv[1] = frcp(s);
            s = eh[16]+eh[17]+eh[18]+eh[19]+eh[20]+eh[21]+eh[22]+eh[23]; iv[2] = frcp(s);
            s = eh[24]+eh[25]+eh[26]+eh[27]+eh[28]+eh[29]+eh[30]+eh[31]; iv[3] = frcp(s);
        }
        __syncwarp();   // prior-group row reads done
        {
            uint4* d4 = reinterpret_cast<uint4*>(Su + tid * HST);
#pragma unroll
            for (int k = 0; k < 8; k++) {
                float inv = iv[k >> 1];
                d4[k] = make_uint4(cvt_tf32(eh[4 * k] * inv),
                                   cvt_tf32(eh[4 * k + 1] * inv),
                                   cvt_tf32(eh[4 * k + 2] * inv),
                                   cvt_tf32(eh[4 * k + 3] * inv));
            }
        }
        __syncwarp();

        float dacc[32];

        // ---- FC1 on W1eff (attention folded in) + gelu -> restage tf32 ----
        fc_mma(Su, wb, g, t, lane, sB1, sb1, dacc);
        __syncwarp();
#pragma unroll
        for (int m = 0; m < 2; m++) {
            uint32_t* base0 = Su + (wb + m * 16 + g) * HST + 2 * t;
            uint32_t* base2 = base0 + 8 * HST;
#pragma unroll
            for (int nt = 0; nt < 4; nt++) {
                float* d = dacc + m * 16 + nt * 4;
                float2 f01 = unpk(gelu2(pack2(d[0], d[1])));
                float2 f23 = unpk(gelu2(pack2(d[2], d[3])));
                *reinterpret_cast<uint2*>(base0 + nt * 8) =
                    make_uint2(cvt_tf32(f01.x), cvt_tf32(f01.y));
                *reinterpret_cast<uint2*>(base2 + nt * 8) =
                    make_uint2(cvt_tf32(f23.x), cvt_tf32(f23.y));
            }
        }
        __syncwarp();

        // ---- FC2 (mma) + gelu -> stage h rows (f32) ----
        fc_mma(Su, wb, g, t, lane, sB2, sb2, dacc);
        __syncwarp();
#pragma unroll
        for (int m = 0; m < 2; m++) {
            float* base0 = hS + (wb + m * 16 + g) * HST + 2 * t;
            float* base2 = base0 + 8 * HST;
#pragma unroll
            for (int nt = 0; nt < 4; nt++) {
                float* d = dacc + m * 16 + nt * 4;
                float2 f01 = unpk(gelu2(pack2(d[0], d[1])));
                float2 f23 = unpk(gelu2(pack2(d[2], d[3])));
                *reinterpret_cast<float2*>(base0 + nt * 8) = f01;
                *reinterpret_cast<float2*>(base2 + nt * 8) = f23;
            }
        }
        __syncwarp();

        if (!LAST) {
            const float4* s4 = reinterpret_cast<const float4*>(hS + tid * HST);
#pragma unroll
            for (int k = 0; k < 8; k++) {
                float4 v = s4[k];
                outb[(size_t)(4 * k + 0) * Ln + l] = __expf(v.x);
                outb[(size_t)(4 * k + 1) * Ln + l] = __expf(v.y);
                outb[(size_t)(4 * k + 2) * Ln + l] = __expf(v.z);
                outb[(size_t)(4 * k + 3) * Ln + l] = __expf(v.w);
            }
            accum_stats(hS, lane, q, m0, m1, m2, m3, sacc);
            __syncwarp();
        } else {
            const float* p = hS + q * 32 * HST;
#pragma unroll 8
            for (int s = 0; s < 32; s++) { pacc += p[lane]; p += HST; }
            __syncwarp();
        }
    }

    if (!LAST) {
        stats_atomic_out(hS, g_kvraw + ((size_t)(BUFIN + 1) * Bn + b) * 288,
                         tid, m0, m1, m2, m3, sacc);
    } else {
        __syncthreads();
        hS[q * 32 + lane] = pacc;
        __syncthreads();
        if (tid < 32)
            g_pool[(size_t)(b * NCH + ch) * 32 + tid] =
                hS[tid] + hS[32 + tid] + hS[64 + tid] + hS[96 + tid];
    }
}

// ---------------------------------------------------------------------------
// Kernel 3: head (pool-finish, Linear, BN(eval), GELU, Linear)
// ---------------------------------------------------------------------------
__global__ __launch_bounds__(32) void final_kernel(
        const float* __restrict__ Wh, const float* __restrict__ bh,
        const float* __restrict__ gamma, const float* __restrict__ beta,
        const float* __restrict__ mu, const float* __restrict__ var,
        const float* __restrict__ Wf, const float* __restrict__ bf,
        float* __restrict__ out) {
    int b = threadIdx.x;
    if (b >= Bn) return;
    float p[32];
#pragma unroll
    for (int c = 0; c < 32; c++) {
        float sum = 0.f;
        for (int ch = 0; ch < NCH; ch++)
            sum += g_pool[(size_t)(b * NCH + ch) * 32 + c];
        p[c] = sum * (1.0f / (float)Ln);
    }
    float z[32];
#pragma unroll
    for (int j = 0; j < 32; j++) {
        float sv = bh[j];
#pragma unroll
        for (int c = 0; c < 32; c++) sv += p[c] * Wh[c * 32 + j];
        sv = (sv - mu[j]) * rsqrtf(var[j] + 1e-5f) * gamma[j] + beta[j];
        z[j] = 0.5f * sv * (1.0f + erff(sv * 0.7071067811865476f));
    }
    for (int k = 0; k < 10; k++) {
        float sv = bf[k];
#pragma unroll
        for (int j = 0; j < 32; j++) sv += z[j] * Wf[j * 10 + k];
        out[b * 10 + k] = sv;
    }
}

// ---------------------------------------------------------------------------
extern "C" void kernel_launch(void* const* d_in, const int* in_sizes, int n_in,
                              void* d_out, int out_size) {
    const float* x    = (const float*)d_in[0];
    const float* fcW1 = (const float*)d_in[1];
    const float* fcb1 = (const float*)d_in[2];
    const float* fcW2 = (const float*)d_in[3];
    const float* fcb2 = (const float*)d_in[4];
    const float* Wh   = (const float*)d_in[5];
    const float* bh   = (const float*)d_in[6];
    const float* gam  = (const float*)d_in[7];
    const float* bet  = (const float*)d_in[8];
    const float* mu   = (const float*)d_in[9];
    const float* var  = (const float*)d_in[10];
    const float* Wf   = (const float*)d_in[11];
    const float* bf   = (const float*)d_in[12];
    float* out = (float*)d_out;

    dim3 grid(NCH, Bn);
    zero_kernel<<<(3 * Bn * 288 + 255) / 256, 256>>>();
    stats_x_kernel<<<grid, NTH>>>(x);
    token_kernel<0, false, true ><<<grid, NTH>>>(x, fcW1, fcb1, fcW2, fcb2);
    token_kernel<1, false, false><<<grid, NTH>>>(nullptr, fcW1 + 1024, fcb1 + 32,
                                                 fcW2 + 1024, fcb2 + 32);
    token_kernel<2, true,  false><<<grid, NTH>>>(nullptr, fcW1 + 2048, fcb1 + 64,
                                                 fcW2 + 2048, fcb2 + 64);
    final_kernel<<<1, 32>>>(Wh, bh, gam, bet, mu, var, Wf, bf, out);
}